// round 3
// baseline (speedup 1.0000x reference)
#include <cuda_runtime.h>

// DCT_26688926778120: grayscale + 8x8 blockwise 2D DCT-II (unnormalized)
// x: (B=8, C=3, T=32, H=256, W=256) fp32 -> out: (B, T, 1024, 8, 8) fp32
//
// One CTA of 256 threads handles one (b, t, block-row): 8 rows x 256 cols
// of grayscale = 32 blocks of 8x8. HBM-bound: ~265 MB of traffic total.

#define SM_STRIDE 257  // 257 % 32 == 1 -> conflict-free row AND column access

__global__ __launch_bounds__(256) void dct_kernel(
    const float* __restrict__ x, float* __restrict__ out)
{
    // Unnormalized DCT-II matrix D[k][n] = 2*cos(pi*(2n+1)*k/16),
    // as compile-time literals so ptxas emits FFMA-with-immediate.
    #define B1 1.96157056f
    #define B2 1.84775907f
    #define B3 1.66293922f
    #define B4 1.41421356f
    #define B5 1.11114047f
    #define B6 0.76536686f
    #define B7 0.39018064f
    constexpr float D[8][8] = {
        { 2.0f,  2.0f,  2.0f,  2.0f,  2.0f,  2.0f,  2.0f,  2.0f},
        {  B1,    B3,    B5,    B7,   -B7,   -B5,   -B3,   -B1 },
        {  B2,    B6,   -B6,   -B2,   -B2,   -B6,    B6,    B2 },
        {  B3,   -B7,   -B1,   -B5,    B5,    B1,    B7,   -B3 },
        {  B4,   -B4,   -B4,    B4,    B4,   -B4,   -B4,    B4 },
        {  B5,   -B1,    B7,    B3,   -B3,   -B7,    B1,   -B5 },
        {  B6,   -B2,    B2,   -B6,   -B6,    B2,   -B2,    B6 },
        {  B7,   -B5,    B3,   -B1,    B1,   -B3,    B5,   -B7 },
    };

    __shared__ float sm[8 * SM_STRIDE];

    const int cta = blockIdx.x;       // cta = ((b*32 + t)*32 + hb)
    const int hb  = cta & 31;
    const int bt  = cta >> 5;         // b*32 + t
    const int tid = threadIdx.x;

    // Input base for (b, c=0, t), row hb*8. Channel stride = T*H*W.
    const size_t IMG   = 256u * 256u;       // 65536
    const size_t CSTRD = 32u * IMG;         // T*H*W = 2097152
    const int b = bt >> 5;
    const int t = bt & 31;
    const float* p0 = x + ((size_t)(b * 3) * 32 + t) * IMG + (size_t)(hb * 8) * 256;
    const float* p1 = p0 + CSTRD;
    const float* p2 = p1 + CSTRD;

    // ---- Stage 1: grayscale, coalesced float4 streaming loads, stage to smem ----
    const float4* v0 = (const float4*)p0;
    const float4* v1 = (const float4*)p1;
    const float4* v2 = (const float4*)p2;
    #pragma unroll
    for (int i = 0; i < 2; i++) {
        int idx4 = tid + i * 256;         // 0..511 float4s (2048 floats)
        int row  = idx4 >> 6;             // 64 float4 per 256-wide row
        int col4 = idx4 & 63;
        float4 a   = __ldcs(v0 + idx4);   // read-once stream: evict-first
        float4 bch = __ldcs(v1 + idx4);
        float4 c   = __ldcs(v2 + idx4);
        float g0 = fmaf(0.2989f, a.x, fmaf(0.587f, bch.x, 0.114f * c.x));
        float g1 = fmaf(0.2989f, a.y, fmaf(0.587f, bch.y, 0.114f * c.y));
        float g2 = fmaf(0.2989f, a.z, fmaf(0.587f, bch.z, 0.114f * c.z));
        float g3 = fmaf(0.2989f, a.w, fmaf(0.587f, bch.w, 0.114f * c.w));
        float* s = sm + row * SM_STRIDE + col4 * 4;
        s[0] = g0; s[1] = g1; s[2] = g2; s[3] = g3;
    }
    __syncthreads();

    const int j = tid >> 3;   // block column 0..31
    const int r = tid & 7;    // row within block (pass A) / output col l (pass B)

    // ---- Pass A: row DCT (Y = X * D^T), in place; thread owns its 8 cells ----
    {
        float xr[8], y[8];
        float* s = sm + r * SM_STRIDE + j * 8;
        #pragma unroll
        for (int n = 0; n < 8; n++) xr[n] = s[n];
        #pragma unroll
        for (int k = 0; k < 8; k++) {
            float acc = 0.0f;
            #pragma unroll
            for (int n = 0; n < 8; n++) acc = fmaf(D[k][n], xr[n], acc);
            y[k] = acc;
        }
        #pragma unroll
        for (int k = 0; k < 8; k++) s[k] = y[k];
    }
    __syncthreads();

    // ---- Pass B: column DCT (out = D * Y); thread (j, l) does column l ----
    {
        const int l = r;
        float yc[8], o[8];
        #pragma unroll
        for (int rr = 0; rr < 8; rr++) yc[rr] = sm[rr * SM_STRIDE + j * 8 + l];
        #pragma unroll
        for (int k = 0; k < 8; k++) {
            float acc = 0.0f;
            #pragma unroll
            for (int rr = 0; rr < 8; rr++) acc = fmaf(D[k][rr], yc[rr], acc);
            o[k] = acc;
        }
        // out linear index: ((b*32+t)*1024 + hb*32 + j)*64 + k*8 + l
        //                 = (cta*32 + j)*64 + k*8 + l
        float* po = out + ((size_t)cta * 32 + j) * 64 + l;
        #pragma unroll
        for (int k = 0; k < 8; k++) __stcs(po + k * 8, o[k]);  // write-once stream
    }
}

extern "C" void kernel_launch(void* const* d_in, const int* in_sizes, int n_in,
                              void* d_out, int out_size)
{
    const float* x = (const float*)d_in[0];
    float* out = (float*)d_out;
    // Grid: B*T*(H/8) = 8*32*32 = 8192 CTAs, 256 threads each.
    dct_kernel<<<8192, 256>>>(x, out);
}